// round 12
// baseline (speedup 1.0000x reference)
#include <cuda_runtime.h>
#include <cuda_bf16.h>
#include <cstdint>
#include <math.h>

// AR(16), batch=4096, steps=8192, segment-parallel (stable system: |char
// roots| >= 1.1 => state decays <= 0.909/step). 64 time segments; segments
// 1..63 start from zero state and warm up on the 128 preceding noise steps
// (residual ~5e-6 << 1e-3 gate).
//
// R11 = R8 resubmit (infra failure, never measured):
//   - NSEG 32 -> 64 (SEGLEN 128, WARM 128): warps 4096 -> 8192, occ ~50%
//   - flush vectorized: 4x STG.128 per thread instead of 16x STG.32
// Keeps: 3-stage cp.async ring, age-ordered 4-cyc recurrence chain,
// scalar 1 batch-row/thread, in-place smem staging + transposed flush.

#define AR_N     16
#define BATCH    4096
#define STEPS    8192
#define TNOISE   (STEPS - AR_N)   /* 8176 */
#define NSEG     64
#define SEGLEN   128              /* last segment: 8176 - 63*128 = 112 */
#define WARM     128              /* 8 blocks of 16 */
#define BT       128              /* threads per block = batch rows per block */
#define NPAD     132              /* smem row stride (floats) */
#define NSTAGE   3

__device__ __forceinline__ void cp16(unsigned dst, const void* src) {
    asm volatile("cp.async.cg.shared.global [%0], [%1], 16;\n" :: "r"(dst), "l"(src));
}

// 16 recurrence steps. h[(k+i)&15]: i=0 oldest ... 15 newest. 13 oldest terms
// tree-summed across 4 accumulators; 3 serial tail FMAs end on y_{t-1} so the
// loop-carried chain is one 4-cycle FMA.
template <bool EMIT>
__device__ __forceinline__ void steps16(float h[AR_N], float* __restrict__ sb,
                                        const float c[AR_N], float nstd, int tid)
{
#pragma unroll
    for (int k = 0; k < AR_N; k++) {
        float e  = sb[k * NPAD + tid];
        float a0 = e * nstd;
        a0 = fmaf(c[0], h[(k + 0) & 15], a0);
        float a1 = c[1] * h[(k + 1) & 15];
        float a2 = c[2] * h[(k + 2) & 15];
        float a3 = c[3] * h[(k + 3) & 15];
        a0 = fmaf(c[4],  h[(k + 4)  & 15], a0);
        a1 = fmaf(c[5],  h[(k + 5)  & 15], a1);
        a2 = fmaf(c[6],  h[(k + 6)  & 15], a2);
        a3 = fmaf(c[7],  h[(k + 7)  & 15], a3);
        a0 = fmaf(c[8],  h[(k + 8)  & 15], a0);
        a1 = fmaf(c[9],  h[(k + 9)  & 15], a1);
        a2 = fmaf(c[10], h[(k + 10) & 15], a2);
        a3 = fmaf(c[11], h[(k + 11) & 15], a3);
        a0 = fmaf(c[12], h[(k + 12) & 15], a0);
        float t = (a0 + a1) + (a2 + a3);
        t = fmaf(c[13], h[(k + 13) & 15], t);        // y_{t-3}
        t = fmaf(c[14], h[(k + 14) & 15], t);        // y_{t-2}
        float nv = fmaf(c[15], h[(k + 15) & 15], t); // y_{t-1}: 4-cyc chain
        h[k & 15] = nv;
        if (EMIT) sb[k * NPAD + tid] = nv;
    }
}

__global__ void __launch_bounds__(BT) ar_segmented_kernel(
    const float* __restrict__ iv,     // (BATCH, 16)
    const float* __restrict__ coef,   // (16,)
    const float* __restrict__ lns,    // (1,)
    const float* __restrict__ noise,  // (TNOISE, BATCH)
    float* __restrict__ out)          // (BATCH, STEPS)
{
    __shared__ __align__(16) float nbuf[NSTAGE][AR_N][NPAD];   // ~25.3 KB

    const int tid = threadIdx.x;
    const int s   = blockIdx.y;
    const int rowbase = blockIdx.x * BT;
    const int b   = rowbase + tid;
    const int t0  = s * SEGLEN;
    const int len = (s == NSEG - 1) ? (TNOISE - t0) : SEGLEN;  // 128 or 112
    const float nstd = expf(lns[0]);

    float c[AR_N];
#pragma unroll
    for (int i = 0; i < AR_N; i++) c[i] = __ldg(&coef[i]);

    float h[AR_N];
    int warmblk, tstart;
    if (s == 0) {
        warmblk = 0; tstart = 0;
#pragma unroll
        for (int i = 0; i < AR_N; i++) {
            h[i] = iv[b * AR_N + i];
            out[(size_t)b * STEPS + i] = h[i];
        }
    } else {
        warmblk = WARM / AR_N;  // 8
        tstart  = t0 - WARM;
#pragma unroll
        for (int i = 0; i < AR_N; i++) h[i] = 0.f;
    }
    const int nblk = warmblk + len / AR_N;  // 8 / 16 / 15

    // cp.async mapping: 16 rows x 128 floats = 8 KB/stage; 4 x 16B per thread
    const int krow = tid >> 5;          // +0,4,8,12
    const int fcol = (tid & 31) * 4;
    const float* gsrc0 = noise + (size_t)rowbase + fcol;
    const unsigned smb = (unsigned)__cvta_generic_to_shared(&nbuf[0][0][0]);

    auto issue_blk = [&](int stg, int trow) {
        const float* g = gsrc0 + (size_t)trow * BATCH;
        unsigned d = smb + (unsigned)(stg * (AR_N * NPAD) + krow * NPAD + fcol) * 4u;
#pragma unroll
        for (int jj = 0; jj < 4; jj++)
            cp16(d + (unsigned)(jj * 4 * NPAD) * 4u,
                 g + (size_t)(krow + jj * 4) * BATCH);
    };

    // prologue: fill stages for blocks 0 and 1
    issue_blk(0, tstart);
    asm volatile("cp.async.commit_group;\n");
    if (nblk > 1) {
        issue_blk(1, tstart + AR_N);
        asm volatile("cp.async.commit_group;\n");
    }

#pragma unroll 1
    for (int blk = 0; blk < nblk; blk++) {
        if (blk + 1 < nblk) asm volatile("cp.async.wait_group 1;\n");
        else                asm volatile("cp.async.wait_group 0;\n");
        __syncthreads();   // stage blk%3 complete & visible; also orders last
                           // iteration's reads of stage (blk+2)%3 before refill

        if (blk + 2 < nblk) {
            issue_blk((blk + 2) % NSTAGE, tstart + (blk + 2) * AR_N);
            asm volatile("cp.async.commit_group;\n");
        }

        float* sb = &nbuf[blk % NSTAGE][0][0];
        if (blk >= warmblk) {
            steps16<true>(h, sb, c, nstd, tid);
            __syncthreads();   // y writes visible before transposed reads
            const int outbase = AR_N + t0 + (blk - warmblk) * AR_N;
            // vectorized transposed flush: 512 quads; lane-quads cover one
            // row's 16 consecutive outputs (64B) -> full sectors, STG.128
#pragma unroll
            for (int j = 0; j < 4; j++) {
                int q    = j * BT + tid;
                int row  = q >> 2;            // batch row within block 0..127
                int col4 = (q & 3) * 4;       // time quad 0,4,8,12
                float4 v;
                v.x = sb[(col4 + 0) * NPAD + row];
                v.y = sb[(col4 + 1) * NPAD + row];
                v.z = sb[(col4 + 2) * NPAD + row];
                v.w = sb[(col4 + 3) * NPAD + row];
                __stcs(reinterpret_cast<float4*>(
                           &out[(size_t)(rowbase + row) * STEPS + outbase + col4]), v);
            }
        } else {
            steps16<false>(h, sb, c, nstd, tid);
        }
    }
}

extern "C" void kernel_launch(void* const* d_in, const int* in_sizes, int n_in,
                              void* d_out, int out_size)
{
    const float* iv    = (const float*)d_in[0];
    const float* coef  = (const float*)d_in[1];
    const float* lns   = (const float*)d_in[2];
    const float* noise = (const float*)d_in[3];
    float* out = (float*)d_out;

    dim3 grid(BATCH / BT, NSEG);
    ar_segmented_kernel<<<grid, BT>>>(iv, coef, lns, noise, out);
}

// round 14
// speedup vs baseline: 1.1412x; 1.1412x over previous
#include <cuda_runtime.h>
#include <cuda_bf16.h>
#include <cstdint>
#include <math.h>

// AR(16), batch=4096, steps=8192. Segment-parallel over time: the system is
// stable (|char roots| <= 1/1.1 => decay 0.909/step), so segments 1..31 start
// from a zero state and warm up on the 160 preceding noise steps (residual
// ~1e-5, far under the 1e-3 gate; accuracy verified in earlier rounds).
//
// R12 = R5 (measured-best structure: NSEG=32, 2-stage cp.async ping-pong,
// symmetric 4-accumulator dot product) + two isolated deltas:
//   - WARM 192 -> 160 (-5% work, accuracy-verified)
//   - vectorized transposed flush: 4x STG.128 per thread (was 16x STG.32)

#define AR_N     16
#define BATCH    4096
#define STEPS    8192
#define TNOISE   (STEPS - AR_N)   /* 8176 */
#define NSEG     32
#define SEGLEN   256              /* last segment: 8176 - 31*256 = 240 */
#define WARM     160              /* 10 blocks of 16 */
#define BT       128              /* threads per block = batch rows per block */
#define NPAD     132              /* smem row stride (floats): 16B-aligned, low-conflict */

__device__ __forceinline__ void cp16(unsigned dst_smem, const void* src_gmem)
{
    asm volatile("cp.async.cg.shared.global [%0], [%1], 16;\n"
                 :: "r"(dst_smem), "l"(src_gmem));
}

// 16 recurrence steps. e[k] read from smem (bank = (4k+tid)%32 -> conflict-free
// across a warp), y_k overwrites the same slot when EMIT. Symmetric
// 4-accumulator tree (R5's measured-best formulation).
template <bool EMIT>
__device__ __forceinline__ void steps16(float h[AR_N], float* __restrict__ sb,
                                        const float c[AR_N], float nstd, int tid)
{
#pragma unroll
    for (int k = 0; k < AR_N; k++) {
        float ek = sb[k * NPAD + tid];
        float a0 = ek * nstd, a1 = 0.f, a2 = 0.f, a3 = 0.f;
#pragma unroll
        for (int i = 0; i < AR_N; i += 4) {
            a0 = fmaf(c[i + 0], h[(k + i + 0) & (AR_N - 1)], a0);
            a1 = fmaf(c[i + 1], h[(k + i + 1) & (AR_N - 1)], a1);
            a2 = fmaf(c[i + 2], h[(k + i + 2) & (AR_N - 1)], a2);
            a3 = fmaf(c[i + 3], h[(k + i + 3) & (AR_N - 1)], a3);
        }
        float nv = (a0 + a1) + (a2 + a3);
        h[k & (AR_N - 1)] = nv;
        if (EMIT) sb[k * NPAD + tid] = nv;
    }
}

__global__ void __launch_bounds__(BT) ar_segmented_kernel(
    const float* __restrict__ iv,     // (BATCH, 16)
    const float* __restrict__ coef,   // (16,)
    const float* __restrict__ lns,    // (1,)
    const float* __restrict__ noise,  // (TNOISE, BATCH)
    float* __restrict__ out)          // (BATCH, STEPS)
{
    __shared__ __align__(16) float nbuf[2][AR_N][NPAD];   // 16.9 KB, double-buffered

    const int tid = threadIdx.x;
    const int s   = blockIdx.y;
    const int rowbase = blockIdx.x * BT;
    const int b   = rowbase + tid;
    const int t0  = s * SEGLEN;
    const int len = (s == NSEG - 1) ? (TNOISE - t0) : SEGLEN;  // 256 or 240
    const float nstd = expf(lns[0]);

    float c[AR_N];
#pragma unroll
    for (int i = 0; i < AR_N; i++) c[i] = __ldg(&coef[i]);

    float h[AR_N];
    int warmblk, tstart;
    if (s == 0) {
        warmblk = 0; tstart = 0;
#pragma unroll
        for (int i = 0; i < AR_N; i++) {
            h[i] = iv[b * AR_N + i];
            out[(size_t)b * STEPS + i] = h[i];
        }
    } else {
        warmblk = WARM / AR_N;  // 10
        tstart  = t0 - WARM;
#pragma unroll
        for (int i = 0; i < AR_N; i++) h[i] = 0.f;
    }
    const int nblk = warmblk + len / AR_N;  // 16 / 26 / 25

    // per-thread cp.async mapping: 4 chunks of 16B; row k = (tid>>5)+4*jj,
    // float column = (tid&31)*4 within this block's 128 batch rows
    const int krow = tid >> 5;
    const int fcol = (tid & 31) * 4;
    const float* gsrc0 = noise + (size_t)rowbase + fcol;
    const unsigned smb = (unsigned)__cvta_generic_to_shared(&nbuf[0][0][0]);

    auto issue_blk = [&](int buf, int trow) {
        const float* g = gsrc0 + (size_t)trow * BATCH;
        unsigned d = smb + (unsigned)(buf * (AR_N * NPAD) + krow * NPAD + fcol) * 4u;
#pragma unroll
        for (int jj = 0; jj < 4; jj++)
            cp16(d + (unsigned)(jj * 4 * NPAD) * 4u,
                 g + (size_t)(krow + jj * 4) * BATCH);
    };

    // prologue: block 0 into buffer 0
    issue_blk(0, tstart);
    asm volatile("cp.async.commit_group;\n");

#pragma unroll 1
    for (int blk = 0; blk < nblk; blk++) {
        const int p = blk & 1;
        if (blk + 1 < nblk) {
            issue_blk(p ^ 1, tstart + (blk + 1) * AR_N);
            asm volatile("cp.async.commit_group;\n");
            asm volatile("cp.async.wait_group 1;\n");
        } else {
            asm volatile("cp.async.wait_group 0;\n");
        }
        __syncthreads();   // buffer p complete & visible; prior flush of p done

        float* sb = &nbuf[p][0][0];
        if (blk >= warmblk) {
            steps16<true>(h, sb, c, nstd, tid);
            __syncthreads();   // y writes visible before transposed reads
            const int outbase = AR_N + t0 + (blk - warmblk) * AR_N;
            // vectorized transposed flush: 512 quads; each thread gathers a
            // 4-wide time quad for one batch row and stores one STG.128.
#pragma unroll
            for (int j = 0; j < 4; j++) {
                int q    = j * BT + tid;
                int row  = q >> 2;            // batch row within block 0..127
                int col4 = (q & 3) * 4;       // time quad 0,4,8,12
                float4 v;
                v.x = sb[(col4 + 0) * NPAD + row];
                v.y = sb[(col4 + 1) * NPAD + row];
                v.z = sb[(col4 + 2) * NPAD + row];
                v.w = sb[(col4 + 3) * NPAD + row];
                __stcs(reinterpret_cast<float4*>(
                           &out[(size_t)(rowbase + row) * STEPS + outbase + col4]), v);
            }
        } else {
            steps16<false>(h, sb, c, nstd, tid);
        }
        __syncthreads();   // all reads of buffer p done before next cp.async overwrite
    }
}

extern "C" void kernel_launch(void* const* d_in, const int* in_sizes, int n_in,
                              void* d_out, int out_size)
{
    const float* iv    = (const float*)d_in[0];
    const float* coef  = (const float*)d_in[1];
    const float* lns   = (const float*)d_in[2];
    const float* noise = (const float*)d_in[3];
    float* out = (float*)d_out;

    dim3 grid(BATCH / BT, NSEG);
    ar_segmented_kernel<<<grid, BT>>>(iv, coef, lns, noise, out);
}

// round 15
// speedup vs baseline: 1.2070x; 1.0576x over previous
#include <cuda_runtime.h>
#include <cuda_bf16.h>
#include <cstdint>
#include <math.h>

// AR(16), batch=4096, steps=8192. Segment-parallel over time (stable system:
// |char roots| >= 1.1 => decay <= 0.909/step). 32 segments; segments 1..31
// start from zero and warm up on the 128 preceding noise steps (residual
// ~5e-6; accuracy verified at WARM=128 in an earlier round).
//
// R13 vs R12 (e2e 65.2us):
//   - fully warp-local pipeline: each warp owns batch rows / smem columns
//     [32w, 32w+32); cp.async fill, compute, and transposed flush never cross
//     warps -> ALL block barriers removed from the main loop (syncwarp only).
//   - WARM 160 -> 128 (-7.5% work, accuracy-verified).

#define AR_N     16
#define BATCH    4096
#define STEPS    8192
#define TNOISE   (STEPS - AR_N)   /* 8176 */
#define NSEG     32
#define SEGLEN   256              /* last segment: 8176 - 31*256 = 240 */
#define WARM     128              /* 8 blocks of 16 */
#define BT       128              /* threads per block = batch rows per block */
#define NPAD     132              /* smem row stride (floats) */

__device__ __forceinline__ void cp16(unsigned dst_smem, const void* src_gmem)
{
    asm volatile("cp.async.cg.shared.global [%0], [%1], 16;\n"
                 :: "r"(dst_smem), "l"(src_gmem));
}

// 16 recurrence steps; symmetric 4-accumulator tree (measured-best form).
// e[k] at sb[k*NPAD + tid]: per warp, banks (4k + tid) % 32 -> conflict-free.
template <bool EMIT>
__device__ __forceinline__ void steps16(float h[AR_N], float* __restrict__ sb,
                                        const float c[AR_N], float nstd, int tid)
{
#pragma unroll
    for (int k = 0; k < AR_N; k++) {
        float ek = sb[k * NPAD + tid];
        float a0 = ek * nstd, a1 = 0.f, a2 = 0.f, a3 = 0.f;
#pragma unroll
        for (int i = 0; i < AR_N; i += 4) {
            a0 = fmaf(c[i + 0], h[(k + i + 0) & (AR_N - 1)], a0);
            a1 = fmaf(c[i + 1], h[(k + i + 1) & (AR_N - 1)], a1);
            a2 = fmaf(c[i + 2], h[(k + i + 2) & (AR_N - 1)], a2);
            a3 = fmaf(c[i + 3], h[(k + i + 3) & (AR_N - 1)], a3);
        }
        float nv = (a0 + a1) + (a2 + a3);
        h[k & (AR_N - 1)] = nv;
        if (EMIT) sb[k * NPAD + tid] = nv;
    }
}

__global__ void __launch_bounds__(BT) ar_segmented_kernel(
    const float* __restrict__ iv,     // (BATCH, 16)
    const float* __restrict__ coef,   // (16,)
    const float* __restrict__ lns,    // (1,)
    const float* __restrict__ noise,  // (TNOISE, BATCH)
    float* __restrict__ out)          // (BATCH, STEPS)
{
    __shared__ __align__(16) float nbuf[2][AR_N][NPAD];   // 16.9 KB

    const int tid   = threadIdx.x;
    const int lane  = tid & 31;
    const int cbase = tid & ~31;      // 32 * warp-id: this warp's row/col base
    const int s     = blockIdx.y;
    const int rowbase = blockIdx.x * BT;
    const int b     = rowbase + tid;
    const int t0    = s * SEGLEN;
    const int len   = (s == NSEG - 1) ? (TNOISE - t0) : SEGLEN;  // 256 or 240
    const float nstd = expf(lns[0]);

    float c[AR_N];
#pragma unroll
    for (int i = 0; i < AR_N; i++) c[i] = __ldg(&coef[i]);

    float h[AR_N];
    int warmblk, tstart;
    if (s == 0) {
        warmblk = 0; tstart = 0;
#pragma unroll
        for (int i = 0; i < AR_N; i++) {
            h[i] = iv[b * AR_N + i];
            out[(size_t)b * STEPS + i] = h[i];
        }
    } else {
        warmblk = WARM / AR_N;  // 8
        tstart  = t0 - WARM;
#pragma unroll
        for (int i = 0; i < AR_N; i++) h[i] = 0.f;
    }
    const int nblk = warmblk + len / AR_N;  // 16 / 24 / 23

    // warp-local cp.async: warp w fills smem columns [32w, 32w+32) only.
    // Per instruction: lane groups of 8 cover 128B contiguous per time row.
    const unsigned smb = (unsigned)__cvta_generic_to_shared(&nbuf[0][0][0]);
    auto issue_blk = [&](int buf, int trow) {
#pragma unroll
        for (int jj = 0; jj < 4; jj++) {
            int cch = jj * 32 + lane;           // chunk 0..127 within warp tile
            int row = cch >> 3;                 // time row 0..15
            int fc  = cbase + (cch & 7) * 4;    // float col within block
            unsigned d = smb + (unsigned)(buf * (AR_N * NPAD) + row * NPAD + fc) * 4u;
            cp16(d, noise + (size_t)(trow + row) * BATCH + rowbase + fc);
        }
    };

    issue_blk(0, tstart);
    asm volatile("cp.async.commit_group;\n");

#pragma unroll 1
    for (int blk = 0; blk < nblk; blk++) {
        const int p = blk & 1;
        if (blk + 1 < nblk) {
            issue_blk(p ^ 1, tstart + (blk + 1) * AR_N);
            asm volatile("cp.async.commit_group;\n");
            asm volatile("cp.async.wait_group 1;\n");
        } else {
            asm volatile("cp.async.wait_group 0;\n");
        }
        __syncwarp();   // warp's cp.async data visible warp-wide

        float* sb = &nbuf[p][0][0];
        if (blk >= warmblk) {
            steps16<true>(h, sb, c, nstd, tid);
            __syncwarp();   // staged y visible for transposed reads
            const int outbase = AR_N + t0 + (blk - warmblk) * AR_N;
            // warp-local transposed flush: 32 rows x 16 cols, 4 STG.128/lane;
            // lane quads cover 64B contiguous per row.
#pragma unroll
            for (int j = 0; j < 4; j++) {
                int q    = j * 32 + lane;
                int rloc = cbase + (q >> 2);     // row within block
                int col4 = (q & 3) * 4;          // time quad 0,4,8,12
                float4 v;
                v.x = sb[(col4 + 0) * NPAD + rloc];
                v.y = sb[(col4 + 1) * NPAD + rloc];
                v.z = sb[(col4 + 2) * NPAD + rloc];
                v.w = sb[(col4 + 3) * NPAD + rloc];
                __stcs(reinterpret_cast<float4*>(
                           &out[(size_t)(rowbase + rloc) * STEPS + outbase + col4]), v);
            }
        } else {
            steps16<false>(h, sb, c, nstd, tid);
        }
        __syncwarp();   // warp's reads of buffer p done before next refill of p
    }
}

extern "C" void kernel_launch(void* const* d_in, const int* in_sizes, int n_in,
                              void* d_out, int out_size)
{
    const float* iv    = (const float*)d_in[0];
    const float* coef  = (const float*)d_in[1];
    const float* lns   = (const float*)d_in[2];
    const float* noise = (const float*)d_in[3];
    float* out = (float*)d_out;

    dim3 grid(BATCH / BT, NSEG);
    ar_segmented_kernel<<<grid, BT>>>(iv, coef, lns, noise, out);
}